// round 3
// baseline (speedup 1.0000x reference)
#include <cuda_runtime.h>
#include <cstdint>

#define N_GRAPHS 256
#define N_NODES  100000
#define N_EDGES  1000000
#define EMB      64
#define EMB_RBF  16

// ---------------- device scratch (no allocations allowed) ----------------
__device__ float        g_M[EMB * EMB_RBF];    // M = W2 * diag(W_out) * W_rbf^T  [j][k]
__device__ float        g_acc6[N_GRAPHS * 6];  // xx, yy, zz, xy, xz, yz per graph
__device__ unsigned int g_cnt[N_GRAPHS];
__device__ int          g_ei64;                // edge_index (and batch) is int64?

typedef unsigned long long ull;

// ---------------- packed f32x2 helpers (FFMA2 — PTX only) ----------------
__device__ __forceinline__ ull pack2(float a, float b) {
    ull r; asm("mov.b64 %0, {%1, %2};" : "=l"(r) : "f"(a), "f"(b)); return r;
}
__device__ __forceinline__ void unpack2(ull v, float& a, float& b) {
    asm("mov.b64 {%0, %1}, %2;" : "=f"(a), "=f"(b) : "l"(v));
}
__device__ __forceinline__ ull fma2(ull a, ull b, ull c) {
    ull d; asm("fma.rn.f32x2 %0, %1, %2, %3;" : "=l"(d) : "l"(a), "l"(b), "l"(c)); return d;
}

__device__ __forceinline__ int load_idx(const void* p, int i, int is64) {
    if (is64) return (int)((const long long*)p)[i];
    return ((const int*)p)[i];
}

// ---------------- 0. dtype detection (int64 vs int32) ----------------
// edge_index values are random in [0, 100000): for an int32 buffer the odd
// 32-bit words are edge values (non-zero w.h.p.); for int64 they are the
// always-zero high words. batch shares edge_index's dtype (same jax pipeline);
// batch itself is sorted (leading zeros) so it CANNOT be detected directly.
__global__ void detect_kernel(const void* ei) {
    if (threadIdx.x == 0 && blockIdx.x == 0) {
        const int* p = (const int*)ei;
        int all0 = 1;
        for (int i = 0; i < 64; i++) if (p[2 * i + 1] != 0) { all0 = 0; break; }
        g_ei64 = all0;
    }
}

// ---------------- 1. zero accumulators ----------------
__global__ void zero_kernel() {
    int i = blockIdx.x * blockDim.x + threadIdx.x;
    if (i < N_GRAPHS * 6) g_acc6[i] = 0.0f;
    if (i < N_GRAPHS)     g_cnt[i] = 0u;
}

// ---------------- 2. fold W2, W_out, W_rbf into M [64,16] ----------------
// M[j][k] = sum_m W2[j][m] * Wout[m] * W_rbf[k][m]
__global__ void prep_kernel(const float* __restrict__ W2,
                            const float* __restrict__ Wrbf,
                            const float* __restrict__ Wout) {
    int t = threadIdx.x;          // 1024 threads
    int j = t >> 4, k = t & 15;
    float acc = 0.0f;
    #pragma unroll 8
    for (int m = 0; m < EMB; m++)
        acc += W2[j * EMB + m] * Wout[m] * Wrbf[k * EMB + m];
    g_M[j * EMB_RBF + k] = acc;
}

// ---------------- 3. per-graph edge counts ----------------
__global__ void count_kernel(const void* __restrict__ edge_index,
                             const void* __restrict__ batch) {
    __shared__ unsigned int h[N_GRAPHS];
    for (int i = threadIdx.x; i < N_GRAPHS; i += blockDim.x) h[i] = 0u;
    __syncthreads();
    int is64 = g_ei64;
    int stride = gridDim.x * blockDim.x;
    for (int e = blockIdx.x * blockDim.x + threadIdx.x; e < N_EDGES; e += stride) {
        int node = load_idx(edge_index, e, is64);
        node = min(max(node, 0), N_NODES - 1);
        int g = load_idx(batch, node, is64);
        g = min(max(g, 0), N_GRAPHS - 1);
        atomicAdd(&h[g], 1u);
    }
    __syncthreads();
    for (int i = threadIdx.x; i < N_GRAPHS; i += blockDim.x)
        if (h[i]) atomicAdd(&g_cnt[i], h[i]);
}

// ---------------- 4. main fused kernel ----------------
__global__ void __launch_bounds__(128, 4)
main_kernel(const float* __restrict__ edge_emb,
            const void*  __restrict__ edge_index,
            const float* __restrict__ distance_vec,
            const void*  __restrict__ batch,
            const float* __restrict__ rbf,
            const float* __restrict__ W1) {
    __shared__ __align__(16) float sW1[EMB * EMB];     // raw row-major W1 [k][j]
    __shared__ __align__(16) float sM[EMB * EMB_RBF];  // M [j][k]
    for (int i = threadIdx.x; i < EMB * EMB; i += blockDim.x) sW1[i] = W1[i];
    for (int i = threadIdx.x; i < EMB * EMB_RBF; i += blockDim.x) sM[i] = g_M[i];
    __syncthreads();
    const ull* sW1u = (const ull*)sW1;   // pair (W1[k][2j], W1[k][2j+1]) at [k*32+j]
    const ull* sMu  = (const ull*)sM;    // pair (M[j][2k], M[j][2k+1])   at [j*8+k]

    const int is64 = g_ei64;
    const int stride = gridDim.x * blockDim.x;

    #pragma unroll 1
    for (int e = blockIdx.x * blockDim.x + threadIdx.x; e < N_EDGES; e += stride) {
        const float4* Erow = (const float4*)(edge_emb + (size_t)e * EMB);

        // ---- h = silu(E @ W1) : 64 outputs as 32 packed pairs ----
        ull acc[32];
        #pragma unroll
        for (int j = 0; j < 32; j++) acc[j] = 0ull;

        float4 ev = Erow[0];
        #pragma unroll 1
        for (int kc = 0; kc < 16; kc++) {
            float4 evn = Erow[(kc < 15) ? (kc + 1) : 15];   // preload next chunk
            const ull* w = sW1u + kc * 4 * 32;
            ull ek;
            ek = pack2(ev.x, ev.x);
            #pragma unroll
            for (int j = 0; j < 32; j++) acc[j] = fma2(ek, w[j], acc[j]);
            ek = pack2(ev.y, ev.y);
            #pragma unroll
            for (int j = 0; j < 32; j++) acc[j] = fma2(ek, w[32 + j], acc[j]);
            ek = pack2(ev.z, ev.z);
            #pragma unroll
            for (int j = 0; j < 32; j++) acc[j] = fma2(ek, w[64 + j], acc[j]);
            ek = pack2(ev.w, ev.w);
            #pragma unroll
            for (int j = 0; j < 32; j++) acc[j] = fma2(ek, w[96 + j], acc[j]);
            ev = evn;
        }

        // ---- silu in place ----
        #pragma unroll
        for (int j = 0; j < 32; j++) {
            float x0, x1; unpack2(acc[j], x0, x1);
            float s0 = __fdividef(x0, 1.0f + __expf(-x0));
            float s1 = __fdividef(x1, 1.0f + __expf(-x1));
            acc[j] = pack2(s0, s1);
        }

        // ---- q = h @ M : 16 outputs as 8 packed pairs ----
        ull q[8];
        #pragma unroll
        for (int k = 0; k < 8; k++) q[k] = 0ull;
        #pragma unroll 4
        for (int jp = 0; jp < 32; jp++) {
            float h0, h1; unpack2(acc[jp], h0, h1);
            const ull* mrow = sMu + (2 * jp) * 8;
            ull b = pack2(h0, h0);
            #pragma unroll
            for (int k = 0; k < 8; k++) q[k] = fma2(b, mrow[k], q[k]);
            b = pack2(h1, h1);
            #pragma unroll
            for (int k = 0; k < 8; k++) q[k] = fma2(b, mrow[8 + k], q[k]);
        }

        // ---- s = q . rbf[e] ----
        const float4* Rrow = (const float4*)(rbf + (size_t)e * EMB_RBF);
        float rv[16];
        *(float4*)&rv[0]  = Rrow[0];
        *(float4*)&rv[4]  = Rrow[1];
        *(float4*)&rv[8]  = Rrow[2];
        *(float4*)&rv[12] = Rrow[3];
        float s = 0.0f;
        #pragma unroll
        for (int k = 0; k < 8; k++) {
            float qa, qb; unpack2(q[k], qa, qb);
            s = fmaf(rv[2 * k], qa, s);
            s = fmaf(rv[2 * k + 1], qb, s);
        }

        // ---- geometry: sym = (s/||d||) * d d^T ; accumulate 6 unique ----
        int node = load_idx(edge_index, e, is64);
        node = min(max(node, 0), N_NODES - 1);
        int g = load_idx(batch, node, is64);
        g = min(max(g, 0), N_GRAPHS - 1);
        float dx = distance_vec[3 * e + 0];
        float dy = distance_vec[3 * e + 1];
        float dz = distance_vec[3 * e + 2];
        float coef = s * rsqrtf(dx * dx + dy * dy + dz * dz);
        float* ag = g_acc6 + g * 6;
        atomicAdd(ag + 0, coef * dx * dx);
        atomicAdd(ag + 1, coef * dy * dy);
        atomicAdd(ag + 2, coef * dz * dz);
        atomicAdd(ag + 3, coef * dx * dy);
        atomicAdd(ag + 4, coef * dx * dz);
        atomicAdd(ag + 5, coef * dy * dz);
    }
}

// ---------------- 5. finalize: divide by counts, expand to 3x3 ----------------
__global__ void finalize_kernel(float* __restrict__ out) {
    int g = blockIdx.x * blockDim.x + threadIdx.x;
    if (g >= N_GRAPHS) return;
    unsigned int c = g_cnt[g];
    float inv = c ? (1.0f / (float)c) : 0.0f;
    float xx = g_acc6[g * 6 + 0] * inv;
    float yy = g_acc6[g * 6 + 1] * inv;
    float zz = g_acc6[g * 6 + 2] * inv;
    float xy = g_acc6[g * 6 + 3] * inv;
    float xz = g_acc6[g * 6 + 4] * inv;
    float yz = g_acc6[g * 6 + 5] * inv;
    float* o = out + g * 9;
    o[0] = xx; o[1] = xy; o[2] = xz;
    o[3] = xy; o[4] = yy; o[5] = yz;
    o[6] = xz; o[7] = yz; o[8] = zz;
}

// ---------------- launcher ----------------
extern "C" void kernel_launch(void* const* d_in, const int* in_sizes, int n_in,
                              void* d_out, int out_size) {
    // Identify inputs by unique element counts (robust to ordering).
    // W1/W2 both have 4096 elements: dict order puts W1 first.
    int i_ee = 0, i_ei = 1, i_dv = 2, i_b = 4, i_rbf = 5,
        i_w1 = 6, i_w2 = 7, i_wr = 8, i_wo = 9;
    int seen4096 = 0;
    for (int i = 0; i < n_in; i++) {
        int s = in_sizes[i];
        if      (s == 64000000) i_ee = i;
        else if (s == 2000000)  i_ei = i;
        else if (s == 3000000)  i_dv = i;
        else if (s == 100000)   i_b  = i;
        else if (s == 16000000) i_rbf = i;
        else if (s == 4096)     { if (seen4096++ == 0) i_w1 = i; else i_w2 = i; }
        else if (s == 1024)     i_wr = i;
        else if (s == 64)       i_wo = i;
        // 2304 = lattice (unused)
    }

    const float* edge_emb     = (const float*)d_in[i_ee];
    const void*  edge_index   = d_in[i_ei];
    const float* distance_vec = (const float*)d_in[i_dv];
    const void*  batch        = d_in[i_b];
    const float* rbf          = (const float*)d_in[i_rbf];
    const float* W1           = (const float*)d_in[i_w1];
    const float* W2           = (const float*)d_in[i_w2];
    const float* W_rbf        = (const float*)d_in[i_wr];
    const float* W_out        = (const float*)d_in[i_wo];
    float* out = (float*)d_out;

    detect_kernel<<<1, 32>>>(edge_index);
    zero_kernel<<<6, 256>>>();
    prep_kernel<<<1, 1024>>>(W2, W_rbf, W_out);
    count_kernel<<<512, 256>>>(edge_index, batch);

    const int threads = 128;
    const int ept = 4;  // edges per thread
    int blocks = (N_EDGES + threads * ept - 1) / (threads * ept);
    main_kernel<<<blocks, threads>>>(edge_emb, edge_index, distance_vec, batch, rbf, W1);

    finalize_kernel<<<1, 256>>>(out);
    (void)out_size;
}

// round 6
// speedup vs baseline: 4.6751x; 4.6751x over previous
#include <cuda_runtime.h>
#include <cuda_bf16.h>
#include <cstdint>

#define N_GRAPHS 256
#define N_NODES  100000
#define N_EDGES  1000000
#define EMB      64
#define EMB_RBF  16
#define TILE_M   128
#define N_TILES  ((N_EDGES + TILE_M - 1) / TILE_M)   // 7813
#define HPAD     66                                  // h row pad (floats) -> conflict-free

typedef unsigned long long ull;

// ---------------- device scratch ----------------
__device__ float        g_M[EMB * EMB_RBF];    // M = W2 * diag(W_out) * W_rbf^T  [j][k]
__device__ float        g_acc6[N_GRAPHS * 6];
__device__ unsigned int g_cnt[N_GRAPHS];
__device__ int          g_ei64;

// ---------------- packed f32x2 (FFMA2) ----------------
__device__ __forceinline__ ull pack2(float a, float b) {
    ull r; asm("mov.b64 %0, {%1, %2};" : "=l"(r) : "f"(a), "f"(b)); return r;
}
__device__ __forceinline__ void unpack2(ull v, float& a, float& b) {
    asm("mov.b64 {%0, %1}, %2;" : "=f"(a), "=f"(b) : "l"(v));
}
__device__ __forceinline__ ull fma2(ull a, ull b, ull c) {
    ull d; asm("fma.rn.f32x2 %0, %1, %2, %3;" : "=l"(d) : "l"(a), "l"(b), "l"(c)); return d;
}
__device__ __forceinline__ int load_idx(const void* p, int i, int is64) {
    if (is64) return (int)((const long long*)p)[i];
    return ((const int*)p)[i];
}

// bf16 hi/lo split of two fp32 values -> packed bf16x2 (lo half = first elem)
__device__ __forceinline__ void split_pack(float f0, float f1, uint32_t& hi, uint32_t& lo) {
    uint32_t h;
    asm("cvt.rn.bf16x2.f32 %0, %1, %2;" : "=r"(h) : "f"(f1), "f"(f0));
    float r0 = f0 - __uint_as_float(h << 16);
    float r1 = f1 - __uint_as_float(h & 0xFFFF0000u);
    uint32_t l;
    asm("cvt.rn.bf16x2.f32 %0, %1, %2;" : "=r"(l) : "f"(r1), "f"(r0));
    hi = h; lo = l;
}

// warp-level bf16 MMA: D[16,8] += A[16,16] * B[16,8]
__device__ __forceinline__ void mma_bf16(float* d, const uint32_t* a, uint32_t b0, uint32_t b1) {
    asm volatile(
        "mma.sync.aligned.m16n8k16.row.col.f32.bf16.bf16.f32 "
        "{%0,%1,%2,%3}, {%4,%5,%6,%7}, {%8,%9}, {%0,%1,%2,%3};"
        : "+f"(d[0]), "+f"(d[1]), "+f"(d[2]), "+f"(d[3])
        : "r"(a[0]), "r"(a[1]), "r"(a[2]), "r"(a[3]), "r"(b0), "r"(b1));
}

// ---------------- small kernels ----------------
__global__ void detect_kernel(const void* ei) {
    if (threadIdx.x == 0 && blockIdx.x == 0) {
        const int* p = (const int*)ei;
        int all0 = 1;
        for (int i = 0; i < 64; i++) if (p[2 * i + 1] != 0) { all0 = 0; break; }
        g_ei64 = all0;
    }
}
__global__ void zero_kernel() {
    int i = blockIdx.x * blockDim.x + threadIdx.x;
    if (i < N_GRAPHS * 6) g_acc6[i] = 0.0f;
    if (i < N_GRAPHS)     g_cnt[i] = 0u;
}
__global__ void prep_kernel(const float* __restrict__ W2,
                            const float* __restrict__ Wrbf,
                            const float* __restrict__ Wout) {
    int t = threadIdx.x;
    int j = t >> 4, k = t & 15;
    float acc = 0.0f;
    #pragma unroll 8
    for (int m = 0; m < EMB; m++)
        acc += W2[j * EMB + m] * Wout[m] * Wrbf[k * EMB + m];
    g_M[j * EMB_RBF + k] = acc;
}

// ---------------- dynamic SMEM layout ----------------
#define SM_AF_HI  0                         // 16 tiles * 32 lanes * 16B = 8192
#define SM_AF_LO  8192                      // 8192
#define SM_H      16384                     // 4 warps * 32 edges * HPAD * 4B = 33792
#define SM_M      50176                     // 64*16 fp32 = 4096
#define SM_CNT    54272                     // 256 u32
#define SM_ACC    55296                     // 256*6 fp32 = 6144
#define SM_TOTAL  61440

// ---------------- main fused kernel ----------------
__global__ void __launch_bounds__(128)
main_kernel(const float* __restrict__ edge_emb,
            const void*  __restrict__ edge_index,
            const float* __restrict__ distance_vec,
            const void*  __restrict__ batch,
            const float* __restrict__ rbf,
            const float* __restrict__ W1) {
    extern __shared__ char smem[];
    const int tid  = threadIdx.x;
    const int wid  = tid >> 5;
    const int lane = tid & 31;
    const int is64 = g_ei64;

    uint32_t* afh = (uint32_t*)(smem + SM_AF_HI);
    uint32_t* afl = (uint32_t*)(smem + SM_AF_LO);

    // ---- prologue: precompute A fragments (W1^T hi/lo), M, histograms ----
    // A = W1^T : A[m][k] = W1[k*64 + m].  Fragment regs per (mt,kt,lane):
    //   a0:(r0,k0..k0+1) a1:(r1,k0..) a2:(r0,k0+8..) a3:(r1,k0+8..)
    //   r0 = 16*mt + lane/4, r1 = r0+8, k0 = 16*kt + (lane%4)*2
    for (int p = wid; p < 16; p += 4) {
        int mt = p >> 2, kt = p & 3;
        int r0 = 16 * mt + (lane >> 2);
        int r1 = r0 + 8;
        int k0 = 16 * kt + (lane & 3) * 2;
        uint32_t hi[4], lo[4];
        split_pack(W1[(k0    ) * EMB + r0], W1[(k0 + 1) * EMB + r0], hi[0], lo[0]);
        split_pack(W1[(k0    ) * EMB + r1], W1[(k0 + 1) * EMB + r1], hi[1], lo[1]);
        split_pack(W1[(k0 + 8) * EMB + r0], W1[(k0 + 9) * EMB + r0], hi[2], lo[2]);
        split_pack(W1[(k0 + 8) * EMB + r1], W1[(k0 + 9) * EMB + r1], hi[3], lo[3]);
        uint32_t base = (uint32_t)(p * 32 + lane) * 4;
        #pragma unroll
        for (int r = 0; r < 4; r++) { afh[base + r] = hi[r]; afl[base + r] = lo[r]; }
    }
    for (int i = tid; i < EMB * EMB_RBF; i += 128)
        ((float*)(smem + SM_M))[i] = g_M[i];
    for (int i = tid; i < N_GRAPHS; i += 128) ((unsigned int*)(smem + SM_CNT))[i] = 0u;
    for (int i = tid; i < N_GRAPHS * 6; i += 128) ((float*)(smem + SM_ACC))[i] = 0.0f;
    __syncthreads();

    const ull* Mull = (const ull*)(smem + SM_M);
    float* hwarp = (float*)(smem + SM_H) + wid * 32 * HPAD;   // [32 edges][HPAD]

    for (int tile = blockIdx.x; tile < N_TILES; tile += gridDim.x) {
        const int base = tile * TILE_M + wid * 32;   // this warp's 32 edges

        // ---- stage 1: 4 passes of 8 edges, mma.sync bf16 3-split ----
        #pragma unroll 1
        for (int pass = 0; pass < 4; pass++) {
            int e0 = base + pass * 8;
            int ec = e0 + (lane >> 2);
            ec = min(ec, N_EDGES - 1);
            const float2* Ep = (const float2*)(edge_emb + (size_t)ec * EMB);

            // B fragments: b[2kt] = k-low pair, b[2kt+1] = k+8 pair
            uint32_t bhi[8], blo[8];
            #pragma unroll
            for (int kt = 0; kt < 4; kt++) {
                float2 x = Ep[(lane & 3) + 8 * kt];
                float2 y = Ep[(lane & 3) + 8 * kt + 4];
                split_pack(x.x, x.y, bhi[2 * kt], blo[2 * kt]);
                split_pack(y.x, y.y, bhi[2 * kt + 1], blo[2 * kt + 1]);
            }

            float d[16];
            #pragma unroll
            for (int i = 0; i < 16; i++) d[i] = 0.0f;

            #pragma unroll
            for (int mt = 0; mt < 4; mt++) {
                #pragma unroll
                for (int kt = 0; kt < 4; kt++) {
                    uint4 ah = *(const uint4*)&afh[((mt * 4 + kt) * 32 + lane) * 4];
                    uint4 al = *(const uint4*)&afl[((mt * 4 + kt) * 32 + lane) * 4];
                    mma_bf16(d + mt * 4, &ah.x, bhi[2 * kt], bhi[2 * kt + 1]);
                    mma_bf16(d + mt * 4, &al.x, bhi[2 * kt], bhi[2 * kt + 1]);
                    mma_bf16(d + mt * 4, &ah.x, blo[2 * kt], blo[2 * kt + 1]);
                }
            }

            // silu + scatter to h[edge][row]
            #pragma unroll
            for (int mt = 0; mt < 4; mt++) {
                #pragma unroll
                for (int r = 0; r < 4; r++) {
                    int row = 16 * mt + (lane >> 2) + 8 * (r >> 1);
                    int el  = pass * 8 + (lane & 3) * 2 + (r & 1);
                    float x = d[mt * 4 + r];
                    hwarp[el * HPAD + row] = __fdividef(x, 1.0f + __expf(-x));
                }
            }
        }
        __syncwarp();

        // ---- stage 2: one edge per lane, FFMA2 h@M + rbf dot + geometry ----
        int e = base + lane;
        if (e < N_EDGES) {
            const float* myh = hwarp + lane * HPAD;

            ull qv[8];
            #pragma unroll
            for (int k = 0; k < 8; k++) qv[k] = 0ull;
            #pragma unroll 8
            for (int jp = 0; jp < 32; jp++) {
                float2 hp = *(const float2*)(myh + 2 * jp);
                const ull* mr = Mull + (2 * jp) * 8;
                ull b = pack2(hp.x, hp.x);
                #pragma unroll
                for (int k = 0; k < 8; k++) qv[k] = fma2(b, mr[k], qv[k]);
                b = pack2(hp.y, hp.y);
                #pragma unroll
                for (int k = 0; k < 8; k++) qv[k] = fma2(b, mr[8 + k], qv[k]);
            }

            const float4* Rr = (const float4*)(rbf + (size_t)e * EMB_RBF);
            float rv[16];
            *(float4*)&rv[0]  = Rr[0];
            *(float4*)&rv[4]  = Rr[1];
            *(float4*)&rv[8]  = Rr[2];
            *(float4*)&rv[12] = Rr[3];
            float s = 0.0f;
            #pragma unroll
            for (int k = 0; k < 8; k++) {
                float qa, qb; unpack2(qv[k], qa, qb);
                s = fmaf(rv[2 * k], qa, s);
                s = fmaf(rv[2 * k + 1], qb, s);
            }

            int node = load_idx(edge_index, e, is64);
            node = min(max(node, 0), N_NODES - 1);
            int g = load_idx(batch, node, is64);
            g = min(max(g, 0), N_GRAPHS - 1);
            float dx = distance_vec[3 * e + 0];
            float dy = distance_vec[3 * e + 1];
            float dz = distance_vec[3 * e + 2];
            float coef = s * rsqrtf(dx * dx + dy * dy + dz * dz);
            float* ag = (float*)(smem + SM_ACC) + g * 6;
            atomicAdd(&((unsigned int*)(smem + SM_CNT))[g], 1u);
            atomicAdd(ag + 0, coef * dx * dx);
            atomicAdd(ag + 1, coef * dy * dy);
            atomicAdd(ag + 2, coef * dz * dz);
            atomicAdd(ag + 3, coef * dx * dy);
            atomicAdd(ag + 4, coef * dx * dz);
            atomicAdd(ag + 5, coef * dy * dz);
        }
        __syncwarp();
    }

    // ---- flush per-CTA partials ----
    __syncthreads();
    for (int i = tid; i < N_GRAPHS; i += 128) {
        unsigned int c = ((unsigned int*)(smem + SM_CNT))[i];
        if (c) atomicAdd(&g_cnt[i], c);
    }
    for (int i = tid; i < N_GRAPHS * 6; i += 128) {
        float v = ((float*)(smem + SM_ACC))[i];
        if (v != 0.0f) atomicAdd(&g_acc6[i], v);
    }
}

// ---------------- finalize ----------------
__global__ void finalize_kernel(float* __restrict__ out) {
    int g = blockIdx.x * blockDim.x + threadIdx.x;
    if (g >= N_GRAPHS) return;
    unsigned int c = g_cnt[g];
    float inv = c ? (1.0f / (float)c) : 0.0f;
    float xx = g_acc6[g * 6 + 0] * inv;
    float yy = g_acc6[g * 6 + 1] * inv;
    float zz = g_acc6[g * 6 + 2] * inv;
    float xy = g_acc6[g * 6 + 3] * inv;
    float xz = g_acc6[g * 6 + 4] * inv;
    float yz = g_acc6[g * 6 + 5] * inv;
    float* o = out + g * 9;
    o[0] = xx; o[1] = xy; o[2] = xz;
    o[3] = xy; o[4] = yy; o[5] = yz;
    o[6] = xz; o[7] = yz; o[8] = zz;
}

// ---------------- launcher ----------------
extern "C" void kernel_launch(void* const* d_in, const int* in_sizes, int n_in,
                              void* d_out, int out_size) {
    int i_ee = 0, i_ei = 1, i_dv = 2, i_b = 4, i_rbf = 5,
        i_w1 = 6, i_w2 = 7, i_wr = 8, i_wo = 9;
    int seen4096 = 0;
    for (int i = 0; i < n_in; i++) {
        int s = in_sizes[i];
        if      (s == 64000000) i_ee = i;
        else if (s == 2000000)  i_ei = i;
        else if (s == 3000000)  i_dv = i;
        else if (s == 100000)   i_b  = i;
        else if (s == 16000000) i_rbf = i;
        else if (s == 4096)     { if (seen4096++ == 0) i_w1 = i; else i_w2 = i; }
        else if (s == 1024)     i_wr = i;
        else if (s == 64)       i_wo = i;
    }

    const float* edge_emb     = (const float*)d_in[i_ee];
    const void*  edge_index   = d_in[i_ei];
    const float* distance_vec = (const float*)d_in[i_dv];
    const void*  batch        = d_in[i_b];
    const float* rbf          = (const float*)d_in[i_rbf];
    const float* W1           = (const float*)d_in[i_w1];
    const float* W2           = (const float*)d_in[i_w2];
    const float* W_rbf        = (const float*)d_in[i_wr];
    const float* W_out        = (const float*)d_in[i_wo];
    float* out = (float*)d_out;

    cudaFuncSetAttribute(main_kernel, cudaFuncAttributeMaxDynamicSharedMemorySize, SM_TOTAL);

    detect_kernel<<<1, 32>>>(edge_index);
    zero_kernel<<<6, 256>>>();
    prep_kernel<<<1, 1024>>>(W2, W_rbf, W_out);

    main_kernel<<<444, 128, SM_TOTAL>>>(edge_emb, edge_index, distance_vec, batch, rbf, W1);

    finalize_kernel<<<1, 256>>>(out);
    (void)out_size;
}